// round 17
// baseline (speedup 1.0000x reference)
#include <cuda_runtime.h>
#include <cuda_fp16.h>
#include <cstdint>
#include <math.h>

// Problem constants
#define BB   2
#define LL   4096
#define EE   512
#define HH   8
#define DD   64
#define WIN  128
#define NTOK (BB*LL)          // 8192
#define QKVN (3*EE)           // 1536

// ---------------------------------------------------------------------------
// Device scratch (half precision dataflow)
// ---------------------------------------------------------------------------
__device__ __half g_Xh[NTOK*EE];                      // x rounded
__device__ __half g_Wq[QKVN*EE];                      // qkv weights (rounded)
__device__ __half g_Wo[EE*EE];                        // out weights (rounded)
__device__ __half g_Qh[BB*HH*LL*DD];                  // Q rounded (scale*log2e)
__device__ __half g_Kh[BB*HH*LL*DD];                  // K rounded [B,H,L,D]
__device__ __half g_Vt[BB*HH*DD*LL];                  // V transposed [B,H,D,L]
__device__ __half g_Oh[BB*LL*EE];                     // attn out (rounded)

// ---------------------------------------------------------------------------
// Helpers
// ---------------------------------------------------------------------------
__device__ __forceinline__ void mma_f16(float* d, const uint32_t* a,
                                        const uint32_t* b) {
    asm volatile(
        "mma.sync.aligned.m16n8k16.row.col.f32.f16.f16.f32 "
        "{%0,%1,%2,%3}, {%4,%5,%6,%7}, {%8,%9}, {%0,%1,%2,%3};"
        : "+f"(d[0]), "+f"(d[1]), "+f"(d[2]), "+f"(d[3])
        : "r"(a[0]), "r"(a[1]), "r"(a[2]), "r"(a[3]),
          "r"(b[0]), "r"(b[1]));
}

#define LDSM4(r0, r1, r2, r3, addr) \
    asm volatile("ldmatrix.sync.aligned.m8n8.x4.shared.b16 {%0,%1,%2,%3}, [%4];" \
                 : "=r"(r0), "=r"(r1), "=r"(r2), "=r"(r3) : "r"(addr))

__device__ __forceinline__ uint32_t pack_h2(__half a, __half b) {
    return (uint32_t)__half_as_ushort(a) | ((uint32_t)__half_as_ushort(b) << 16);
}

__device__ __forceinline__ uint32_t smem_u32(const void* p) {
    uint32_t a;
    asm("{ .reg .u64 t; cvta.to.shared.u64 t, %1; cvt.u32.u64 %0, t; }"
        : "=r"(a) : "l"(p));
    return a;
}
// L2-only (cg): streamed data, don't pollute L1 (LDSM needs its bandwidth)
__device__ __forceinline__ void cp16(uint32_t dst, const void* src) {
    asm volatile("cp.async.cg.shared.global [%0], [%1], 16;"
                 :: "r"(dst), "l"(src));
}
#define CP_COMMIT() asm volatile("cp.async.commit_group;" ::: "memory")

// ---------------------------------------------------------------------------
// Fused prep: round Wq | Wo | X to half in ONE launch (region by linear idx).
// ---------------------------------------------------------------------------
#define WQ_U (QKVN * EE / 4)          // 196608 float4 units
#define WO_U (EE * EE / 4)            // 65536
#define X_U  (NTOK * EE / 4)          // 1048576
#define PREP_BLOCKS ((WQ_U + WO_U + X_U) / 256)

__global__ __launch_bounds__(256) void prep_all(
    const float* __restrict__ wq, const float* __restrict__ wo,
    const float* __restrict__ x)
{
    int u = blockIdx.x * 256 + threadIdx.x;
    const float* src;
    __half* dst;
    int off;
    if (u < WQ_U)              { src = wq; dst = g_Wq; off = u; }
    else if (u < WQ_U + WO_U)  { src = wo; dst = g_Wo; off = u - WQ_U; }
    else                       { src = x;  dst = g_Xh; off = u - WQ_U - WO_U; }
    int i = off * 4;
    float4 v = *reinterpret_cast<const float4*>(&src[i]);
    uint2 o;
    o.x = pack_h2(__float2half_rn(v.x), __float2half_rn(v.y));
    o.y = pack_h2(__float2half_rn(v.z), __float2half_rn(v.w));
    *reinterpret_cast<uint2*>(&dst[i]) = o;
}

// ---------------------------------------------------------------------------
// fp16 m16n8k16 GEMM (QKV projection): C = Xh @ Wq^T + bias, K=512.
//   CTA 128x128, BK=64 (8 chunks), 8 warps, warp tile 64x32.
//   3-stage cp.async pipeline, ldmatrix.x4.  (Proven: ~55-58 us.)
// ---------------------------------------------------------------------------
#define HP   72
#define PLH  (128 * HP)
#define GEMM_SMEM (6 * PLH * 2)         // 108 KB

__global__ __launch_bounds__(256) void qkv_gemm_f16(
    const float* __restrict__ bias)
{
    extern __shared__ __half smh[];
    const uint32_t sbase = smem_u32(smh);

    const int tid = threadIdx.x;
    const int m0 = blockIdx.y * 128;
    const int n0 = blockIdx.x * 128;

    const int w    = tid >> 5;
    const int lane = tid & 31;
    const int g    = lane >> 2;
    const int c    = lane & 3;
    const int rm   = (w >> 2) * 64;
    const int cn   = (w & 3) * 32;

    const int arow = lane & 15;
    const int acol = (lane >> 4) * 8;
    const int bno  = (lane & 7) + ((lane >> 4) << 3);
    const int bko  = ((lane >> 3) & 1) * 8;

    float acc[4][4][4];
    #pragma unroll
    for (int mi = 0; mi < 4; mi++)
        #pragma unroll
        for (int ni = 0; ni < 4; ni++)
            #pragma unroll
            for (int r = 0; r < 4; r++) acc[mi][ni][r] = 0.f;

    const int lrow = tid >> 2;
    const int lcol = (tid & 3) * 16;

    auto issue_chunk = [&](int kc, int p) {
        const __half* a  = g_Xh + (size_t)m0 * EE + kc * 64;
        const __half* bb = g_Wq + (size_t)n0 * EE + kc * 64;
        const uint32_t sb = sbase + (uint32_t)(p * 2 * PLH * 2);
        #pragma unroll
        for (int i = 0; i < 2; i++) {
            int row = lrow + i * 64;
            uint32_t so = (uint32_t)((row * HP + lcol) * 2);
            cp16(sb + so,                a  + (size_t)row * EE + lcol);
            cp16(sb + so + 16,           a  + (size_t)row * EE + lcol + 8);
            cp16(sb + PLH * 2 + so,      bb + (size_t)row * EE + lcol);
            cp16(sb + PLH * 2 + so + 16, bb + (size_t)row * EE + lcol + 8);
        }
    };

    issue_chunk(0, 0); CP_COMMIT();
    issue_chunk(1, 1); CP_COMMIT();

    for (int kc = 0; kc < 8; kc++) {
        const int p = kc % 3;
        if (kc < 7) asm volatile("cp.async.wait_group 1;" ::: "memory");
        else        asm volatile("cp.async.wait_group 0;" ::: "memory");
        __syncthreads();

        if (kc + 2 < 8) {
            issue_chunk(kc + 2, (kc + 2) % 3);
            CP_COMMIT();
        }

        const uint32_t sA = sbase + (uint32_t)(p * 2 * PLH * 2);
        const uint32_t sB = sA + (uint32_t)(PLH * 2);

        #pragma unroll
        for (int ks = 0; ks < 4; ks++) {
            uint32_t af[4][4], bf[4][2];
            #pragma unroll
            for (int mi = 0; mi < 4; mi++) {
                uint32_t ad = sA + (uint32_t)(((rm + mi * 16 + arow) * HP
                                               + ks * 16 + acol) * 2);
                LDSM4(af[mi][0], af[mi][1], af[mi][2], af[mi][3], ad);
            }
            #pragma unroll
            for (int p2 = 0; p2 < 2; p2++) {
                uint32_t bd = sB + (uint32_t)(((cn + p2 * 16 + bno) * HP
                                               + ks * 16 + bko) * 2);
                LDSM4(bf[2 * p2][0], bf[2 * p2][1],
                      bf[2 * p2 + 1][0], bf[2 * p2 + 1][1], bd);
            }
            #pragma unroll
            for (int mi = 0; mi < 4; mi++)
                #pragma unroll
                for (int ni = 0; ni < 4; ni++)
                    mma_f16(acc[mi][ni], af[mi], bf[ni]);
        }
    }

    float bv[4][2];
    #pragma unroll
    for (int ni = 0; ni < 4; ni++) {
        int gn = n0 + cn + ni * 8 + 2 * c;
        bv[ni][0] = bias[gn];
        bv[ni][1] = bias[gn + 1];
    }

    const int gnb = n0 + cn;
    const int sel = gnb >> 9;                  // 0=Q 1=K 2=V
    const int h   = (gnb >> 6) & 7;
    // Q scale folds 1/sqrt(D) AND log2(e) so softmax can use exp2.
    const float QSCALE = 0.125f * 1.4426950408889634f;
    #pragma unroll
    for (int mi = 0; mi < 4; mi++) {
        #pragma unroll
        for (int half = 0; half < 2; half++) {
            int gm  = m0 + rm + mi * 16 + g + half * 8;
            int bat = gm >> 12;
            int l   = gm & (LL - 1);
            #pragma unroll
            for (int ni = 0; ni < 4; ni++) {
                int gn = n0 + cn + ni * 8 + 2 * c;
                int d  = gn & 63;
                float f0 = acc[mi][ni][half * 2 + 0] + bv[ni][0];
                float f1 = acc[mi][ni][half * 2 + 1] + bv[ni][1];
                if (sel == 0) {
                    f0 *= QSCALE; f1 *= QSCALE;
                    size_t rb = (((size_t)(bat * HH + h) * LL) + l) * DD + d;
                    *reinterpret_cast<uint32_t*>(&g_Qh[rb]) =
                        pack_h2(__float2half_rn(f0), __float2half_rn(f1));
                } else if (sel == 1) {
                    size_t rb = (((size_t)(bat * HH + h) * LL) + l) * DD + d;
                    *reinterpret_cast<uint32_t*>(&g_Kh[rb]) =
                        pack_h2(__float2half_rn(f0), __float2half_rn(f1));
                } else {
                    size_t vb = (((size_t)(bat * HH + h) * DD) + d) * LL + l;
                    g_Vt[vb]      = __float2half_rn(f0);
                    g_Vt[vb + LL] = __float2half_rn(f1);
                }
            }
        }
    }
}

// ---------------------------------------------------------------------------
// Out projection, small tile: 64(M)x128(N), BK=64, 8 warps (2x4), warp 32x32.
//   2-stage cp.async, ldmatrix. acc=32 regs -> ~70 regs total -> 3 CTAs/SM.
//   Grid (4, 128) = 512 CTAs: ~2x resident warps vs the 128x128 version.
// ---------------------------------------------------------------------------
#define APLH (64 * HP)                  // A plane halves
#define OUT_STAGE ((APLH + PLH) * 2)    // bytes per stage (A + B)
#define OUT_SMEM  (2 * OUT_STAGE)       // 55.3 KB

__global__ __launch_bounds__(256, 3) void out_gemm_f16(
    const float* __restrict__ bias, float* __restrict__ outp)
{
    extern __shared__ __half smo[];
    const uint32_t sbase = smem_u32(smo);

    const int tid = threadIdx.x;
    const int m0 = blockIdx.y * 64;
    const int n0 = blockIdx.x * 128;

    const int w    = tid >> 5;
    const int lane = tid & 31;
    const int g    = lane >> 2;
    const int c    = lane & 3;
    const int rm   = (w >> 2) * 32;      // 0 / 32
    const int cn   = (w & 3) * 32;

    const int arow = lane & 15;
    const int acol = (lane >> 4) * 8;
    const int bno  = (lane & 7) + ((lane >> 4) << 3);
    const int bko  = ((lane >> 3) & 1) * 8;

    float acc[2][4][4];
    #pragma unroll
    for (int mi = 0; mi < 2; mi++)
        #pragma unroll
        for (int ni = 0; ni < 4; ni++)
            #pragma unroll
            for (int r = 0; r < 4; r++) acc[mi][ni][r] = 0.f;

    auto issue_chunk = [&](int kc, int p) {
        const __half* a  = g_Oh + (size_t)m0 * EE + kc * 64;
        const __half* bb = g_Wo + (size_t)n0 * EE + kc * 64;
        const uint32_t sb = sbase + (uint32_t)(p * OUT_STAGE);
        {   // A: 64 rows x 64 halves = 512 cp16; 2 per thread
            int row = tid >> 2;
            int seg = (tid & 3) * 16;
            uint32_t so = (uint32_t)((row * HP + seg) * 2);
            cp16(sb + so,      a + (size_t)row * EE + seg);
            cp16(sb + so + 16, a + (size_t)row * EE + seg + 8);
        }
        {   // B: 128 rows x 64 halves = 1024 cp16; 4 per thread
            int row = tid >> 1;
            int seg = (tid & 1) * 32;
            uint32_t so = (uint32_t)(APLH * 2 + (row * HP + seg) * 2);
            cp16(sb + so,      bb + (size_t)row * EE + seg);
            cp16(sb + so + 16, bb + (size_t)row * EE + seg + 8);
            cp16(sb + so + 32, bb + (size_t)row * EE + seg + 16);
            cp16(sb + so + 48, bb + (size_t)row * EE + seg + 24);
        }
    };

    issue_chunk(0, 0); CP_COMMIT();

    for (int kc = 0; kc < 8; kc++) {
        const int p = kc & 1;
        asm volatile("cp.async.wait_group 0;" ::: "memory");
        __syncthreads();

        if (kc + 1 < 8) {
            issue_chunk(kc + 1, p ^ 1);
            CP_COMMIT();
        }

        const uint32_t sA = sbase + (uint32_t)(p * OUT_STAGE);
        const uint32_t sB = sA + (uint32_t)(APLH * 2);

        #pragma unroll
        for (int ks = 0; ks < 4; ks++) {
            uint32_t bf[4][2];
            #pragma unroll
            for (int p2 = 0; p2 < 2; p2++) {
                uint32_t bd = sB + (uint32_t)(((cn + p2 * 16 + bno) * HP
                                               + ks * 16 + bko) * 2);
                LDSM4(bf[2 * p2][0], bf[2 * p2][1],
                      bf[2 * p2 + 1][0], bf[2 * p2 + 1][1], bd);
            }
            #pragma unroll
            for (int mi = 0; mi < 2; mi++) {
                uint32_t af[4];
                uint32_t ad = sA + (uint32_t)(((rm + mi * 16 + arow) * HP
                                               + ks * 16 + acol) * 2);
                LDSM4(af[0], af[1], af[2], af[3], ad);
                #pragma unroll
                for (int ni = 0; ni < 4; ni++)
                    mma_f16(acc[mi][ni], af, bf[ni]);
            }
        }
    }

    float bv[4][2];
    #pragma unroll
    for (int ni = 0; ni < 4; ni++) {
        int gn = n0 + cn + ni * 8 + 2 * c;
        bv[ni][0] = bias[gn];
        bv[ni][1] = bias[gn + 1];
    }

    #pragma unroll
    for (int mi = 0; mi < 2; mi++) {
        #pragma unroll
        for (int half = 0; half < 2; half++) {
            int gm = m0 + rm + mi * 16 + g + half * 8;
            #pragma unroll
            for (int ni = 0; ni < 4; ni++) {
                int gn = n0 + cn + ni * 8 + 2 * c;
                float2 o;
                o.x = acc[mi][ni][half * 2 + 0] + bv[ni][0];
                o.y = acc[mi][ni][half * 2 + 1] + bv[ni][1];
                *reinterpret_cast<float2*>(&outp[(size_t)gm * EE + gn]) = o;
            }
        }
    }
}

// ---------------------------------------------------------------------------
// Banded flash attention (round-16 proven config).
// ---------------------------------------------------------------------------
#define AP 72
#define HPL (64 * AP)
#define ATTN_SMEM (6 * HPL * 2)

__global__ __launch_bounds__(128, 4) void attn_mma()
{
    extern __shared__ __half smq[];
    const uint32_t sQ  = smem_u32(smq);
    const uint32_t sP  = sQ + 1 * HPL * 2;
    const uint32_t sKV = sQ + 2 * HPL * 2;
    __half* Qs = smq;

    const int q0 = blockIdx.x * 64;
    const int h  = blockIdx.y;
    const int b  = blockIdx.z;
    const int tid  = threadIdx.x;
    const int w    = tid >> 5;
    const int lane = tid & 31;
    const int g    = lane >> 2;
    const int c    = lane & 3;

    const int arow = lane & 15;
    const int acol = (lane >> 4) * 8;
    const int bno  = (lane & 7) + ((lane >> 4) << 3);
    const int bko  = ((lane >> 3) & 1) * 8;

    const size_t khead = ((size_t)(b * HH + h) * LL) * DD;
    const size_t vhead = ((size_t)(b * HH + h) * DD) * LL;

    #pragma unroll
    for (int i = 0; i < 4; i++) {
        int u = tid + i * 128;
        int row = u >> 3;
        int seg = (u & 7) * 8;
        *reinterpret_cast<uint4*>(&Qs[row * AP + seg]) =
            *reinterpret_cast<const uint4*>(&g_Qh[khead + (size_t)(q0 + row) * DD + seg]);
    }

    const int ch_lo = max(0, (191 - q0) / 64);
    const int ch_hi = min(5, (LL + 128 - q0) / 64);

    auto stage_kv = [&](int ch, int p) {
        const int kcc = q0 - 128 + ch * 64;
        const uint32_t sb = sKV + (uint32_t)(p * 2 * HPL * 2);
        #pragma unroll
        for (int i = 0; i < 4; i++) {
            int u = tid + i * 128;
            int row = u >> 3;
            int seg = (u & 7) * 8;
            uint32_t so = (uint32_t)((row * AP + seg) * 2);
            cp16(sb + so, &g_Kh[khead + (size_t)(kcc + row) * DD + seg]);
            cp16(sb + HPL * 2 + so,
                 &g_Vt[vhead + (size_t)row * LL + kcc + seg]);
        }
    };

    float om[2] = {-1e30f, -1e30f};
    float ol[2] = {0.f, 0.f};
    float oacc[8][4];
    #pragma unroll
    for (int nt = 0; nt < 8; nt++)
        #pragma unroll
        for (int r = 0; r < 4; r++) oacc[nt][r] = 0.f;

    stage_kv(ch_lo, 0); CP_COMMIT();
    __syncthreads();

    const int row_lo = 16 * w + g;
    const int q_lo = q0 + row_lo;
    const int q_hi = q_lo + 8;

    for (int ch = ch_lo; ch < ch_hi; ch++) {
        const int p = (ch - ch_lo) & 1;
        const int kcc = q0 - 128 + ch * 64;
        const uint32_t sK = sKV + (uint32_t)(p * 2 * HPL * 2);
        const uint32_t sV = sK + (uint32_t)(HPL * 2);

        asm volatile("cp.async.wait_group 0;" ::: "memory");
        __syncthreads();

        if (ch + 1 < ch_hi) {
            stage_kv(ch + 1, p ^ 1);
            CP_COMMIT();
        }

        float sacc[8][4];
        #pragma unroll
        for (int nt = 0; nt < 8; nt++)
            #pragma unroll
            for (int r = 0; r < 4; r++) sacc[nt][r] = 0.f;

        #pragma unroll
        for (int ks = 0; ks < 4; ks++) {
            uint32_t af[4], kb2[8][2];
            uint32_t ad = sQ + (uint32_t)(((16 * w + arow) * AP + ks * 16 + acol) * 2);
            LDSM4(af[0], af[1], af[2], af[3], ad);
            #pragma unroll
            for (int p2 = 0; p2 < 4; p2++) {
                uint32_t bd = sK + (uint32_t)(((p2 * 16 + bno) * AP + ks * 16 + bko) * 2);
                LDSM4(kb2[2 * p2][0], kb2[2 * p2][1],
                      kb2[2 * p2 + 1][0], kb2[2 * p2 + 1][1], bd);
            }
            #pragma unroll
            for (int nt = 0; nt < 8; nt++)
                mma_f16(sacc[nt], af, kb2[nt]);
        }

        #pragma unroll
        for (int nt = 0; nt < 8; nt++) {
            #pragma unroll
            for (int r = 0; r < 4; r++) {
                int key = kcc + nt * 8 + 2 * c + (r & 1);
                int q   = (r >> 1) ? q_hi : q_lo;
                int dlt = q - key;
                bool ok = (dlt != 0) && (dlt <= WIN) && (dlt >= -WIN);
                if (!ok) sacc[nt][r] = -1e30f;
            }
        }

        float mx0 = -1e30f, mx1 = -1e30f;
        #pragma unroll
        for (int nt = 0; nt < 8; nt++) {
            mx0 = fmaxf(mx0, fmaxf(sacc[nt][0], sacc[nt][1]));
            mx1 = fmaxf(mx1, fmaxf(sacc[nt][2], sacc[nt][3]));
        }
        mx0 = fmaxf(mx0, __shfl_xor_sync(0xffffffffu, mx0, 1));
        mx0 = fmaxf(mx0, __shfl_xor_sync(0xffffffffu, mx0, 2));
        mx1 = fmaxf(mx1, __shfl_xor_sync(0xffffffffu, mx1, 1));
        mx1 = fmaxf(mx1, __shfl_xor_sync(0xffffffffu, mx1, 2));

        float m0n = fmaxf(om[0], mx0);
        float m1n = fmaxf(om[1], mx1);
        float alpha0 = exp2f(om[0] - m0n);
        float alpha1 = exp2f(om[1] - m1n);

        float sum0 = 0.f, sum1 = 0.f;
        __half* Ph = smq + 1 * HPL;
        #pragma unroll
        for (int nt = 0; nt < 8; nt++) {
            float p0 = exp2f(sacc[nt][0] - m0n);
            float p1 = exp2f(sacc[nt][1] - m0n);
            float p2 = exp2f(sacc[nt][2] - m1n);
            float p3 = exp2f(sacc[nt][3] - m1n);
            sum0 += p0 + p1;
            sum1 += p2 + p3;
            const int pi_lo = row_lo * AP + nt * 8 + 2 * c;
            const int pi_hi = pi_lo + 8 * AP;
            *reinterpret_cast<uint32_t*>(&Ph[pi_lo]) =
                pack_h2(__float2half_rn(p0), __float2half_rn(p1));
            *reinterpret_cast<uint32_t*>(&Ph[pi_hi]) =
                pack_h2(__float2half_rn(p2), __float2half_rn(p3));
        }
        sum0 += __shfl_xor_sync(0xffffffffu, sum0, 1);
        sum0 += __shfl_xor_sync(0xffffffffu, sum0, 2);
        sum1 += __shfl_xor_sync(0xffffffffu, sum1, 1);
        sum1 += __shfl_xor_sync(0xffffffffu, sum1, 2);

        ol[0] = ol[0] * alpha0 + sum0;
        ol[1] = ol[1] * alpha1 + sum1;
        om[0] = m0n;
        om[1] = m1n;

        #pragma unroll
        for (int nt = 0; nt < 8; nt++) {
            oacc[nt][0] *= alpha0;
            oacc[nt][1] *= alpha0;
            oacc[nt][2] *= alpha1;
            oacc[nt][3] *= alpha1;
        }
        __syncwarp();

        #pragma unroll
        for (int ks = 0; ks < 4; ks++) {
            uint32_t af[4], vb2[8][2];
            uint32_t ad = sP + (uint32_t)(((16 * w + arow) * AP + ks * 16 + acol) * 2);
            LDSM4(af[0], af[1], af[2], af[3], ad);
            #pragma unroll
            for (int p2 = 0; p2 < 4; p2++) {
                uint32_t bd = sV + (uint32_t)(((p2 * 16 + bno) * AP + ks * 16 + bko) * 2);
                LDSM4(vb2[2 * p2][0], vb2[2 * p2][1],
                      vb2[2 * p2 + 1][0], vb2[2 * p2 + 1][1], bd);
            }
            #pragma unroll
            for (int nt = 0; nt < 8; nt++)
                mma_f16(oacc[nt], af, vb2[nt]);
        }
    }

    const float inv0 = 1.f / ol[0];
    const float inv1 = 1.f / ol[1];
    const size_t base_lo = ((size_t)(b * LL + q_lo)) * EE + h * DD;
    const size_t base_hi = ((size_t)(b * LL + q_hi)) * EE + h * DD;
    #pragma unroll
    for (int nt = 0; nt < 8; nt++) {
        int d = nt * 8 + 2 * c;
        *reinterpret_cast<uint32_t*>(&g_Oh[base_lo + d]) =
            pack_h2(__float2half_rn(oacc[nt][0] * inv0),
                    __float2half_rn(oacc[nt][1] * inv0));
        *reinterpret_cast<uint32_t*>(&g_Oh[base_hi + d]) =
            pack_h2(__float2half_rn(oacc[nt][2] * inv1),
                    __float2half_rn(oacc[nt][3] * inv1));
    }
}

// ---------------------------------------------------------------------------
// Entry point
// ---------------------------------------------------------------------------
extern "C" void kernel_launch(void* const* d_in, const int* in_sizes, int n_in,
                              void* d_out, int out_size)
{
    const float* x    = (const float*)d_in[0];   // [B,L,E]
    const float* wqkv = (const float*)d_in[1];   // [3E,E]
    const float* bqkv = (const float*)d_in[2];   // [3E]
    const float* wout = (const float*)d_in[3];   // [E,E]
    const float* bout = (const float*)d_in[4];   // [E]
    float* out = (float*)d_out;                  // [B,L,E]

    (void)in_sizes; (void)n_in; (void)out_size;

    cudaFuncSetAttribute(qkv_gemm_f16, cudaFuncAttributeMaxDynamicSharedMemorySize,
                         GEMM_SMEM);
    cudaFuncSetAttribute(out_gemm_f16, cudaFuncAttributeMaxDynamicSharedMemorySize,
                         OUT_SMEM);
    cudaFuncSetAttribute(attn_mma, cudaFuncAttributeMaxDynamicSharedMemorySize,
                         ATTN_SMEM);

    // fused prep
    prep_all<<<PREP_BLOCKS, 256>>>(wqkv, wout, x);

    // QKV projection
    qkv_gemm_f16<<<dim3(QKVN / 128, NTOK / 128), 256, GEMM_SMEM>>>(bqkv);

    // banded attention
    attn_mma<<<dim3(LL / 64, HH, BB), 128, ATTN_SMEM>>>();

    // out projection (small tile, 512 CTAs, 3 CTAs/SM)
    out_gemm_f16<<<dim3(EE / 128, NTOK / 64), 256, OUT_SMEM>>>(bout, out);
}